// round 14
// baseline (speedup 1.0000x reference)
#include <cuda_runtime.h>
#include <cuda_fp16.h>
#include <stdint.h>
#include <math.h>

#define TT 2048
#define BB 2
#define DD 512
#define HH 8
#define DH 64
#define MAXREL 32
#define SCALE_L2E 0.1803368801111244f   // (DH^-0.5) * log2(e)
#define L2E 1.4426950408889634f
#define KT 64                           // keys per attention tile
#define NKT (TT / KT)                   // 32 tiles

// Scratch (allocation-free rule: __device__ globals)
__device__ __half g_Qh[BB * TT * DD];
__device__ __half g_Kh[BB * TT * DD];
__device__ __half g_Vth[BB * HH * DH * TT];   // V transposed [b,h,d,t]
__device__ __half g_AOh[BB * TT * DD];
__device__ __half g_Xh[BB * TT * DD];         // hidden states, half
__device__ __half g_Wth[4 * DD * DD];         // W^T half: [n][k] for q,k,v,o

// ---------------------------------------------------------------------------
// helpers
// ---------------------------------------------------------------------------
__device__ __forceinline__ float ex2(float x) {
    float r;
    asm("ex2.approx.ftz.f32 %0, %1;" : "=f"(r) : "f"(x));
    return r;
}
__device__ __forceinline__ void mma16(float* d, const uint32_t* a, uint32_t b0, uint32_t b1) {
    asm volatile(
        "mma.sync.aligned.m16n8k16.row.col.f32.f16.f16.f32 "
        "{%0,%1,%2,%3}, {%4,%5,%6,%7}, {%8,%9}, {%0,%1,%2,%3};"
        : "+f"(d[0]), "+f"(d[1]), "+f"(d[2]), "+f"(d[3])
        : "r"(a[0]), "r"(a[1]), "r"(a[2]), "r"(a[3]), "r"(b0), "r"(b1));
}
__device__ __forceinline__ void ldsm4(uint32_t& r0, uint32_t& r1, uint32_t& r2, uint32_t& r3,
                                      uint32_t addr) {
    asm volatile("ldmatrix.sync.aligned.m8n8.x4.shared.b16 {%0,%1,%2,%3}, [%4];"
                 : "=r"(r0), "=r"(r1), "=r"(r2), "=r"(r3) : "r"(addr));
}
__device__ __forceinline__ uint32_t packh2(float lo, float hi) {
    __half2 h = __floats2half2_rn(lo, hi);
    return *(uint32_t*)&h;
}
__device__ __forceinline__ uint32_t smem_u32(const void* p) {
    uint32_t a;
    asm("{ .reg .u64 t; cvta.to.shared.u64 t, %1; cvt.u32.u64 %0, t; }" : "=r"(a) : "l"(p));
    return a;
}
__device__ __forceinline__ void cpasync16(uint32_t dst, const void* src) {
    asm volatile("cp.async.cg.shared.global [%0], [%1], 16;" :: "r"(dst), "l"(src));
}
#define CP_COMMIT() asm volatile("cp.async.commit_group;" ::: "memory")
#define CP_WAIT1()  asm volatile("cp.async.wait_group 1;" ::: "memory")

// ---------------------------------------------------------------------------
// Fused prep: z=0..3 -> W[k][n] fp32 -> Wt[n][k] half; z=4 -> hs fp32 -> half
// ---------------------------------------------------------------------------
__global__ void prep_kernel(const float* __restrict__ hs,
                            const float* __restrict__ W0, const float* __restrict__ W1,
                            const float* __restrict__ W2, const float* __restrict__ W3,
                            __half* __restrict__ Xh, __half* __restrict__ Wt)
{
    const int z = blockIdx.z;
    const int tx = threadIdx.x, ty = threadIdx.y;
    if (z == 4) {
        const int tidf = ty * 32 + tx;
        const int gb = blockIdx.y * gridDim.x + blockIdx.x;   // 0..255
        const float4* src = (const float4*)hs;
#pragma unroll
        for (int j = 0; j < 8; j++) {
            int i = gb * 2048 + j * 256 + tidf;
            float4 v = src[i];
            __half2 lo = __floats2half2_rn(v.x, v.y);
            __half2 hi = __floats2half2_rn(v.z, v.w);
            uint2 o = make_uint2(*(uint32_t*)&lo, *(uint32_t*)&hi);
            *(uint2*)&Xh[i * 4] = o;
        }
        return;
    }
    __shared__ __half t[32][33];
    const float* W = (z == 0) ? W0 : (z == 1) ? W1 : (z == 2) ? W2 : W3;
    __half* dst = Wt + (size_t)z * DD * DD;
    const int k0 = blockIdx.x * 32, n0 = blockIdx.y * 32;
#pragma unroll
    for (int i = 0; i < 4; i++)
        t[ty + i * 8][tx] = __float2half(W[(size_t)(k0 + ty + i * 8) * DD + n0 + tx]);
    __syncthreads();
#pragma unroll
    for (int i = 0; i < 4; i++)
        dst[(size_t)(n0 + ty + i * 8) * DD + k0 + tx] = t[tx][ty + i * 8];
}

// ---------------------------------------------------------------------------
// GEMM fp16 (QKV): BM=64, BN=128, BK=64, 128 threads. grid.z selects w/b/out.
// z == vtz -> write output TRANSPOSED per head into Vt [b,h,d,t].
// ---------------------------------------------------------------------------
#define XSP 72                       // halves per row (64 + 8 pad)
#define XT_H (64 * XSP)              // 4608
#define WT_H (128 * XSP)             // 9216
#define GEMM_SMEM_B ((2 * XT_H + 2 * WT_H) * 2 + 512 + 16)
#define NKCH 8

__global__ void __launch_bounds__(128) gemm_f16_kernel(
    const __half* __restrict__ X, const __half* __restrict__ WtBase, int wbase,
    const float* __restrict__ b0p, const float* __restrict__ b1p, const float* __restrict__ b2p,
    void* __restrict__ o0p, void* __restrict__ o1p, void* __restrict__ o2p,
    int out_half, int vtz)
{
    extern __shared__ __align__(16) __half smh[];
    __half* sx = smh;                      // [2][XT_H]
    __half* sw = smh + 2 * XT_H;           // [2][WT_H]
    float* bs = (float*)(smh + 2 * XT_H + 2 * WT_H);
    const uint32_t sxb = smem_u32(sx);
    const uint32_t swb = smem_u32(sw);

    const int z = blockIdx.z;
    const __half* Wt = WtBase + (size_t)(wbase + z) * DD * DD;
    const float* bias = (z == 0) ? b0p : (z == 1) ? b1p : b2p;
    void* Cout = (z == 0) ? o0p : (z == 1) ? o1p : o2p;

    const int tid = threadIdx.x;
    const int lane = tid & 31;
    const int wid = tid >> 5;
    const int wr = wid * 16;
    const int g = lane >> 2, q4 = lane & 3;
    const int m0 = blockIdx.y * 64;
    const int n0 = blockIdx.x * 128;

    const int lr = tid >> 3;            // 0..15
    const int lc = (tid & 7) * 8;       // halves column (16B chunks)

#pragma unroll
    for (int it = 0; it < 4; it++) {
        int r = lr + it * 16;
        cpasync16(sxb + (r * XSP + lc) * 2, &X[(size_t)(m0 + r) * DD + lc]);
    }
#pragma unroll
    for (int it = 0; it < 8; it++) {
        int r = lr + it * 16;
        cpasync16(swb + (r * XSP + lc) * 2, &Wt[(size_t)(n0 + r) * DD + lc]);
    }
    CP_COMMIT();
    if (tid < 128) bs[tid] = bias[n0 + tid];

    float c[16][4];
#pragma unroll
    for (int nt = 0; nt < 16; nt++)
#pragma unroll
        for (int j = 0; j < 4; j++) c[nt][j] = 0.0f;

    for (int ch = 0; ch < NKCH; ch++) {
        if (ch + 1 < NKCH) {
            const int k0 = (ch + 1) * 64;
            const int st = (ch + 1) & 1;
#pragma unroll
            for (int it = 0; it < 4; it++) {
                int r = lr + it * 16;
                cpasync16(sxb + (st * XT_H + r * XSP + lc) * 2, &X[(size_t)(m0 + r) * DD + k0 + lc]);
            }
#pragma unroll
            for (int it = 0; it < 8; it++) {
                int r = lr + it * 16;
                cpasync16(swb + (st * WT_H + r * XSP + lc) * 2, &Wt[(size_t)(n0 + r) * DD + k0 + lc]);
            }
        }
        CP_COMMIT();
        CP_WAIT1();
        __syncthreads();

        const __half* Xs = sx + (ch & 1) * XT_H;
        const __half* Ws = sw + (ch & 1) * WT_H;

#pragma unroll
        for (int ks = 0; ks < 4; ks++) {
            uint32_t a[4];
            const int ac = q4 * 2 + ks * 16;
            a[0] = *(const uint32_t*)&Xs[(wr + g) * XSP + ac];
            a[1] = *(const uint32_t*)&Xs[(wr + g + 8) * XSP + ac];
            a[2] = *(const uint32_t*)&Xs[(wr + g) * XSP + ac + 8];
            a[3] = *(const uint32_t*)&Xs[(wr + g + 8) * XSP + ac + 8];
#pragma unroll
            for (int nt = 0; nt < 16; nt++) {
                uint32_t b0 = *(const uint32_t*)&Ws[(nt * 8 + g) * XSP + ac];
                uint32_t b1 = *(const uint32_t*)&Ws[(nt * 8 + g) * XSP + ac + 8];
                mma16(c[nt], a, b0, b1);
            }
        }
        __syncthreads();
    }

    const int r0 = m0 + wr + g;
    if (z == vtz) {
        __half* stg = smh;   // 128*72 halves, reuse x buffers
        const int rl = wr + g;
#pragma unroll
        for (int nt = 0; nt < 16; nt++) {
            int colL = nt * 8 + q4 * 2;
            stg[colL * 72 + rl] = __float2half(c[nt][0] + bs[colL]);
            stg[(colL + 1) * 72 + rl] = __float2half(c[nt][1] + bs[colL + 1]);
            stg[colL * 72 + rl + 8] = __float2half(c[nt][2] + bs[colL]);
            stg[(colL + 1) * 72 + rl + 8] = __float2half(c[nt][3] + bs[colL + 1]);
        }
        __syncthreads();
        __half* Vt = (__half*)Cout;
        const int bb = m0 >> 11;
        const int t0 = m0 & (TT - 1);
#pragma unroll
        for (int it = 0; it < 8; it++) {
            int cidx = tid + it * 128;
            int colL = cidx >> 3;
            int tc = (cidx & 7) * 8;
            int n = n0 + colL;
            int hh = n >> 6, d = n & 63;
            uint4 v = *(uint4*)&stg[colL * 72 + tc];
            *(uint4*)&Vt[(size_t)((bb * HH + hh) * DH + d) * TT + t0 + tc] = v;
        }
    } else if (out_half) {
        __half* C = (__half*)Cout;
#pragma unroll
        for (int nt = 0; nt < 16; nt++) {
            int col = n0 + nt * 8 + q4 * 2;
            int bcol = nt * 8 + q4 * 2;
            uint32_t p0 = packh2(c[nt][0] + bs[bcol], c[nt][1] + bs[bcol + 1]);
            uint32_t p1 = packh2(c[nt][2] + bs[bcol], c[nt][3] + bs[bcol + 1]);
            *(uint32_t*)&C[(size_t)r0 * DD + col] = p0;
            *(uint32_t*)&C[(size_t)(r0 + 8) * DD + col] = p1;
        }
    } else {
        float* C = (float*)Cout;
#pragma unroll
        for (int nt = 0; nt < 16; nt++) {
            int col = n0 + nt * 8 + q4 * 2;
            int bcol = nt * 8 + q4 * 2;
            *(float2*)&C[(size_t)r0 * DD + col] =
                make_float2(c[nt][0] + bs[bcol], c[nt][1] + bs[bcol + 1]);
            *(float2*)&C[(size_t)(r0 + 8) * DD + col] =
                make_float2(c[nt][2] + bs[bcol], c[nt][3] + bs[bcol + 1]);
        }
    }
}

// ---------------------------------------------------------------------------
// O-projection GEMM: BM=32, BN=128, BK=64, 128 threads (warps 2x2 m16/n64).
// Grid (4, 128) = 512 CTAs. fp32 output.
// ---------------------------------------------------------------------------
#define X2T_H (32 * XSP)             // 2304

__global__ void __launch_bounds__(128) gemm_f16_bm32_kernel(
    const __half* __restrict__ X, const __half* __restrict__ Wt,
    const float* __restrict__ bias, float* __restrict__ C)
{
    __shared__ __align__(16) __half sx[2][X2T_H];
    __shared__ __align__(16) __half sw[2][WT_H];
    __shared__ float bs[128];
    const uint32_t sxb = smem_u32(sx);
    const uint32_t swb = smem_u32(sw);

    const int tid = threadIdx.x;
    const int lane = tid & 31;
    const int wid = tid >> 5;
    const int wm = wid & 1, wn = wid >> 1;
    const int g = lane >> 2, q4 = lane & 3;
    const int m0 = blockIdx.y * 32;
    const int n0 = blockIdx.x * 128;

    const int lr = tid >> 3;            // 0..15
    const int lc = (tid & 7) * 8;

#pragma unroll
    for (int it = 0; it < 2; it++) {
        int r = lr + it * 16;
        cpasync16(sxb + (r * XSP + lc) * 2, &X[(size_t)(m0 + r) * DD + lc]);
    }
#pragma unroll
    for (int it = 0; it < 8; it++) {
        int r = lr + it * 16;
        cpasync16(swb + (r * XSP + lc) * 2, &Wt[(size_t)(n0 + r) * DD + lc]);
    }
    CP_COMMIT();
    if (tid < 128) bs[tid] = bias[n0 + tid];

    float c[8][4];
#pragma unroll
    for (int nt = 0; nt < 8; nt++)
#pragma unroll
        for (int j = 0; j < 4; j++) c[nt][j] = 0.0f;

    for (int ch = 0; ch < NKCH; ch++) {
        if (ch + 1 < NKCH) {
            const int k0 = (ch + 1) * 64;
            const int st = (ch + 1) & 1;
#pragma unroll
            for (int it = 0; it < 2; it++) {
                int r = lr + it * 16;
                cpasync16(sxb + (st * X2T_H + r * XSP + lc) * 2, &X[(size_t)(m0 + r) * DD + k0 + lc]);
            }
#pragma unroll
            for (int it = 0; it < 8; it++) {
                int r = lr + it * 16;
                cpasync16(swb + (st * WT_H + r * XSP + lc) * 2, &Wt[(size_t)(n0 + r) * DD + k0 + lc]);
            }
        }
        CP_COMMIT();
        CP_WAIT1();
        __syncthreads();

        const __half* Xs = sx[ch & 1];
        const __half* Ws = sw[ch & 1];

#pragma unroll
        for (int ks = 0; ks < 4; ks++) {
            uint32_t a[4];
            const int ac = q4 * 2 + ks * 16;
            a[0] = *(const uint32_t*)&Xs[(wm * 16 + g) * XSP + ac];
            a[1] = *(const uint32_t*)&Xs[(wm * 16 + g + 8) * XSP + ac];
            a[2] = *(const uint32_t*)&Xs[(wm * 16 + g) * XSP + ac + 8];
            a[3] = *(const uint32_t*)&Xs[(wm * 16 + g + 8) * XSP + ac + 8];
#pragma unroll
            for (int nt = 0; nt < 8; nt++) {
                uint32_t b0 = *(const uint32_t*)&Ws[(wn * 64 + nt * 8 + g) * XSP + ac];
                uint32_t b1 = *(const uint32_t*)&Ws[(wn * 64 + nt * 8 + g) * XSP + ac + 8];
                mma16(c[nt], a, b0, b1);
            }
        }
        __syncthreads();
    }

    const int r0 = m0 + wm * 16 + g;
#pragma unroll
    for (int nt = 0; nt < 8; nt++) {
        int bcol = wn * 64 + nt * 8 + q4 * 2;
        int col = n0 + bcol;
        *(float2*)&C[(size_t)r0 * DD + col] =
            make_float2(c[nt][0] + bs[bcol], c[nt][1] + bs[bcol + 1]);
        *(float2*)&C[(size_t)(r0 + 8) * DD + col] =
            make_float2(c[nt][2] + bs[bcol], c[nt][3] + bs[bcol + 1]);
    }
}

// ---------------------------------------------------------------------------
// Attention fp16 (R12). Grid (T/128, H, B), 128 threads (4 warps, m32 each).
// ldmatrix.x4 for all K/V B-fragments; direct normalized half O write.
// ---------------------------------------------------------------------------
#define KSP 72
#define AKT_H (KT * KSP)

__global__ void __launch_bounds__(128) attn_f16_kernel(
    const __half* __restrict__ Q, const __half* __restrict__ K,
    const __half* __restrict__ Vt, const float* __restrict__ rb,
    __half* __restrict__ O)
{
    __shared__ __align__(16) __half ks_[2][AKT_H];
    __shared__ __align__(16) __half vs_[2][AKT_H];
    __shared__ float bias_s[72];
    const uint32_t kb = smem_u32(ks_);
    const uint32_t vb = smem_u32(vs_);

    const int tid = threadIdx.x;
    const int lane = tid & 31;
    const int wid = tid >> 5;
    const int wr = wid * 32;
    const int g = lane >> 2, q4 = lane & 3;
    const int q0 = blockIdx.x * 128;
    const int h = blockIdx.y, b = blockIdx.z;
    const int base = b * TT * DD + h * DH;
    const int vtbase = (b * HH + h) * DH * TT;

    const int lr = tid >> 3;
    const int lc = (tid & 7) * 8;

    const int grp = lane >> 3, lrow = lane & 7;
    const int lmoff = (((grp >> 1) * 8 + lrow) * KSP + (grp & 1) * 8) * 2;

#pragma unroll
    for (int it = 0; it < 4; it++) {
        int r = lr + it * 16;
        cpasync16(kb + (r * KSP + lc) * 2, &K[base + r * DD + lc]);
        cpasync16(vb + (r * KSP + lc) * 2, &Vt[vtbase + r * TT + lc]);
    }
    CP_COMMIT();

    if (tid < 2 * MAXREL + 1) bias_s[tid] = rb[h * (2 * MAXREL + 1) + tid] * L2E;
    const float blo = rb[h * (2 * MAXREL + 1)] * L2E;
    const float bhi = rb[h * (2 * MAXREL + 1) + 2 * MAXREL] * L2E;

    uint32_t qf[2][4][4];
#pragma unroll
    for (int ss = 0; ss < 2; ss++) {
        const int r = q0 + wr + ss * 16 + g;
#pragma unroll
        for (int ksi = 0; ksi < 4; ksi++) {
            const int ac = q4 * 2 + ksi * 16;
            qf[ss][ksi][0] = *(const uint32_t*)&Q[base + r * DD + ac];
            qf[ss][ksi][1] = *(const uint32_t*)&Q[base + (r + 8) * DD + ac];
            qf[ss][ksi][2] = *(const uint32_t*)&Q[base + r * DD + ac + 8];
            qf[ss][ksi][3] = *(const uint32_t*)&Q[base + (r + 8) * DD + ac + 8];
        }
    }

    float o[2][8][4];
#pragma unroll
    for (int ss = 0; ss < 2; ss++)
#pragma unroll
        for (int nt = 0; nt < 8; nt++)
#pragma unroll
            for (int j = 0; j < 4; j++) o[ss][nt][j] = 0.0f;
    float ls[2][2] = {{0.f, 0.f}, {0.f, 0.f}};

    for (int kt = 0; kt < NKT; kt++) {
        const int k0 = kt * KT;
        if (kt + 1 < NKT) {
            const int kn = (kt + 1) * KT;
            const int st = (kt + 1) & 1;
#pragma unroll
            for (int it = 0; it < 4; it++) {
                int r = lr + it * 16;
                cpasync16(kb + (st * AKT_H + r * KSP + lc) * 2, &K[base + (kn + r) * DD + lc]);
                cpasync16(vb + (st * AKT_H + r * KSP + lc) * 2, &Vt[vtbase + r * TT + kn + lc]);
            }
        }
        CP_COMMIT();
        CP_WAIT1();
        __syncthreads();

        const uint32_t kaddr = kb + (kt & 1) * AKT_H * 2 + lmoff;
        const uint32_t vaddr = vb + (kt & 1) * AKT_H * 2 + lmoff;

        float s[2][8][4];
#pragma unroll
        for (int ss = 0; ss < 2; ss++)
#pragma unroll
            for (int nt = 0; nt < 8; nt++)
#pragma unroll
                for (int j = 0; j < 4; j++) s[ss][nt][j] = 0.0f;

#pragma unroll
        for (int ksi = 0; ksi < 4; ksi++) {
#pragma unroll
            for (int ntp = 0; ntp < 4; ntp++) {
                uint32_t b0, b1, b2, b3;
                ldsm4(b0, b1, b2, b3, kaddr + (ntp * 16 * KSP + ksi * 16) * 2);
                mma16(s[0][2 * ntp], qf[0][ksi], b0, b1);
                mma16(s[1][2 * ntp], qf[1][ksi], b0, b1);
                mma16(s[0][2 * ntp + 1], qf[0][ksi], b2, b3);
                mma16(s[1][2 * ntp + 1], qf[1][ksi], b2, b3);
            }
        }

        const int dmin = q0 - (k0 + KT - 1);
        const int dmax = q0 + 127 - k0;
        if (dmin >= MAXREL) {
#pragma unroll
            for (int ss = 0; ss < 2; ss++)
#pragma unroll
                for (int nt = 0; nt < 8; nt++)
#pragma unroll
                    for (int j = 0; j < 4; j++)
                        s[ss][nt][j] = ex2(fmaf(s[ss][nt][j], SCALE_L2E, bhi));
        } else if (dmax <= -MAXREL) {
#pragma unroll
            for (int ss = 0; ss < 2; ss++)
#pragma unroll
                for (int nt = 0; nt < 8; nt++)
#pragma unroll
                    for (int j = 0; j < 4; j++)
                        s[ss][nt][j] = ex2(fmaf(s[ss][nt][j], SCALE_L2E, blo));
        } else {
#pragma unroll
            for (int ss = 0; ss < 2; ss++) {
                const int dr0 = q0 + wr + ss * 16 + g;
#pragma unroll
                for (int nt = 0; nt < 8; nt++) {
                    const int c0 = k0 + nt * 8 + q4 * 2;
#pragma unroll
                    for (int j = 0; j < 4; j++) {
                        int rel = (dr0 + ((j >> 1) << 3)) - (c0 + (j & 1));
                        rel = min(max(rel, -MAXREL), MAXREL) + MAXREL;
                        s[ss][nt][j] = ex2(fmaf(s[ss][nt][j], SCALE_L2E, bias_s[rel]));
                    }
                }
            }
        }
#pragma unroll
        for (int ss = 0; ss < 2; ss++)
#pragma unroll
            for (int nt = 0; nt < 8; nt++) {
                ls[ss][0] += s[ss][nt][0] + s[ss][nt][1];
                ls[ss][1] += s[ss][nt][2] + s[ss][nt][3];
            }

#pragma unroll
        for (int ksi = 0; ksi < 4; ksi++) {
            uint32_t a0[4], a1[4];
            a0[0] = packh2(s[0][2 * ksi][0], s[0][2 * ksi][1]);
            a0[1] = packh2(s[0][2 * ksi][2], s[0][2 * ksi][3]);
            a0[2] = packh2(s[0][2 * ksi + 1][0], s[0][2 * ksi + 1][1]);
            a0[3] = packh2(s[0][2 * ksi + 1][2], s[0][2 * ksi + 1][3]);
            a1[0] = packh2(s[1][2 * ksi][0], s[1][2 * ksi][1]);
            a1[1] = packh2(s[1][2 * ksi][2], s[1][2 * ksi][3]);
            a1[2] = packh2(s[1][2 * ksi + 1][0], s[1][2 * ksi + 1][1]);
            a1[3] = packh2(s[1][2 * ksi + 1][2], s[1][2 * ksi + 1][3]);
#pragma unroll
            for (int ntp = 0; ntp < 4; ntp++) {
                uint32_t b0, b1, b2, b3;
                ldsm4(b0, b1, b2, b3, vaddr + (ntp * 16 * KSP + ksi * 16) * 2);
                mma16(o[0][2 * ntp], a0, b0, b1);
                mma16(o[1][2 * ntp], a1, b0, b1);
                mma16(o[0][2 * ntp + 1], a0, b2, b3);
                mma16(o[1][2 * ntp + 1], a1, b2, b3);
            }
        }
        __syncthreads();
    }

#pragma unroll
    for (int ss = 0; ss < 2; ss++) {
#pragma unroll
        for (int j = 0; j < 2; j++) {
            ls[ss][j] += __shfl_xor_sync(0xffffffffu, ls[ss][j], 1);
            ls[ss][j] += __shfl_xor_sync(0xffffffffu, ls[ss][j], 2);
        }
        const float inv0 = 1.0f / ls[ss][0];
        const float inv1 = 1.0f / ls[ss][1];
        const int r0 = q0 + wr + ss * 16 + g;
#pragma unroll
        for (int nt = 0; nt < 8; nt++) {
            int col = nt * 8 + q4 * 2;
            uint32_t p0 = packh2(o[ss][nt][0] * inv0, o[ss][nt][1] * inv0);
            uint32_t p1 = packh2(o[ss][nt][2] * inv1, o[ss][nt][3] * inv1);
            *(uint32_t*)&O[base + r0 * DD + col] = p0;
            *(uint32_t*)&O[base + (r0 + 8) * DD + col] = p1;
        }
    }
}

// ---------------------------------------------------------------------------
extern "C" void kernel_launch(void* const* d_in, const int* in_sizes, int n_in,
                              void* d_out, int out_size)
{
    const float* hs = (const float*)d_in[0];
    const float* Wq = (const float*)d_in[1];
    const float* bq = (const float*)d_in[2];
    const float* Wk = (const float*)d_in[3];
    const float* bk = (const float*)d_in[4];
    const float* Wv = (const float*)d_in[5];
    const float* bv = (const float*)d_in[6];
    const float* Wo = (const float*)d_in[7];
    const float* bo = (const float*)d_in[8];
    const float* rb = (const float*)d_in[9];

    __half *pQ, *pK, *pVt, *pAO, *pX, *pW;
    cudaGetSymbolAddress((void**)&pQ, g_Qh);
    cudaGetSymbolAddress((void**)&pK, g_Kh);
    cudaGetSymbolAddress((void**)&pVt, g_Vth);
    cudaGetSymbolAddress((void**)&pAO, g_AOh);
    cudaGetSymbolAddress((void**)&pX, g_Xh);
    cudaGetSymbolAddress((void**)&pW, g_Wth);

    cudaFuncSetAttribute(gemm_f16_kernel,
                         cudaFuncAttributeMaxDynamicSharedMemorySize, GEMM_SMEM_B);

    // prep: z=0..3 weight transpose+cvt, z=4 hidden-state cvt
    prep_kernel<<<dim3(DD / 32, DD / 32, 5), dim3(32, 8)>>>(hs, Wq, Wk, Wv, Wo, pX, pW);

    // Fused Q/K/V projections; z==2 writes V transposed straight into Vt
    gemm_f16_kernel<<<dim3(DD / 128, BB * TT / 64, 3), 128, GEMM_SMEM_B>>>(
        pX, pW, 0, bq, bk, bv, pQ, pK, pVt, 1, 2);

    // Single-pass attention, direct half O
    attn_f16_kernel<<<dim3(TT / 128, HH, BB), 128>>>(pQ, pK, pVt, rb, pAO);

    // Output projection: BM=32 variant, grid 512
    gemm_f16_bm32_kernel<<<dim3(DD / 128, BB * TT / 32), 128>>>(
        pAO, pW + 3 * DD * DD, bo, (float*)d_out);
}

// round 15
// speedup vs baseline: 1.5485x; 1.5485x over previous
#include <cuda_runtime.h>
#include <cuda_fp16.h>
#include <stdint.h>
#include <math.h>

#define TT 2048
#define BB 2
#define DD 512
#define HH 8
#define DH 64
#define MAXREL 32
#define SCALE_L2E 0.1803368801111244f   // (DH^-0.5) * log2(e)
#define L2E 1.4426950408889634f
#define KT 64                           // keys per attention tile
#define NKT (TT / KT)                   // 32 tiles

// Scratch (allocation-free rule: __device__ globals)
__device__ __half g_Qh[BB * TT * DD];
__device__ __half g_Kh[BB * TT * DD];
__device__ __half g_Vth[BB * HH * DH * TT];   // V transposed [b,h,d,t]
__device__ __half g_AOh[BB * TT * DD];
__device__ __half g_Xh[BB * TT * DD];         // hidden states, half
__device__ __half g_Wth[4 * DD * DD];         // W^T half: [n][k] for q,k,v,o

// ---------------------------------------------------------------------------
// helpers
// ---------------------------------------------------------------------------
__device__ __forceinline__ float ex2(float x) {
    float r;
    asm("ex2.approx.ftz.f32 %0, %1;" : "=f"(r) : "f"(x));
    return r;
}
__device__ __forceinline__ void mma16(float* d, const uint32_t* a, uint32_t b0, uint32_t b1) {
    asm volatile(
        "mma.sync.aligned.m16n8k16.row.col.f32.f16.f16.f32 "
        "{%0,%1,%2,%3}, {%4,%5,%6,%7}, {%8,%9}, {%0,%1,%2,%3};"
        : "+f"(d[0]), "+f"(d[1]), "+f"(d[2]), "+f"(d[3])
        : "r"(a[0]), "r"(a[1]), "r"(a[2]), "r"(a[3]), "r"(b0), "r"(b1));
}
__device__ __forceinline__ void ldsm4(uint32_t& r0, uint32_t& r1, uint32_t& r2, uint32_t& r3,
                                      uint32_t addr) {
    asm volatile("ldmatrix.sync.aligned.m8n8.x4.shared.b16 {%0,%1,%2,%3}, [%4];"
                 : "=r"(r0), "=r"(r1), "=r"(r2), "=r"(r3) : "r"(addr));
}
__device__ __forceinline__ uint32_t packh2(float lo, float hi) {
    __half2 h = __floats2half2_rn(lo, hi);
    return *(uint32_t*)&h;
}
__device__ __forceinline__ uint32_t smem_u32(const void* p) {
    uint32_t a;
    asm("{ .reg .u64 t; cvta.to.shared.u64 t, %1; cvt.u32.u64 %0, t; }" : "=r"(a) : "l"(p));
    return a;
}
__device__ __forceinline__ void cpasync16(uint32_t dst, const void* src) {
    asm volatile("cp.async.cg.shared.global [%0], [%1], 16;" :: "r"(dst), "l"(src));
}
#define CP_COMMIT() asm volatile("cp.async.commit_group;" ::: "memory")
#define CP_WAIT1()  asm volatile("cp.async.wait_group 1;" ::: "memory")
#define CP_WAIT2()  asm volatile("cp.async.wait_group 2;" ::: "memory")

// ---------------------------------------------------------------------------
// Fused prep: z=0..3 -> W[k][n] fp32 -> Wt[n][k] half; z=4 -> hs fp32 -> half
// ---------------------------------------------------------------------------
__global__ void prep_kernel(const float* __restrict__ hs,
                            const float* __restrict__ W0, const float* __restrict__ W1,
                            const float* __restrict__ W2, const float* __restrict__ W3,
                            __half* __restrict__ Xh, __half* __restrict__ Wt)
{
    const int z = blockIdx.z;
    const int tx = threadIdx.x, ty = threadIdx.y;
    if (z == 4) {
        const int tidf = ty * 32 + tx;
        const int gb = blockIdx.y * gridDim.x + blockIdx.x;   // 0..255
        const float4* src = (const float4*)hs;
#pragma unroll
        for (int j = 0; j < 8; j++) {
            int i = gb * 2048 + j * 256 + tidf;
            float4 v = src[i];
            __half2 lo = __floats2half2_rn(v.x, v.y);
            __half2 hi = __floats2half2_rn(v.z, v.w);
            uint2 o = make_uint2(*(uint32_t*)&lo, *(uint32_t*)&hi);
            *(uint2*)&Xh[i * 4] = o;
        }
        return;
    }
    __shared__ __half t[32][33];
    const float* W = (z == 0) ? W0 : (z == 1) ? W1 : (z == 2) ? W2 : W3;
    __half* dst = Wt + (size_t)z * DD * DD;
    const int k0 = blockIdx.x * 32, n0 = blockIdx.y * 32;
#pragma unroll
    for (int i = 0; i < 4; i++)
        t[ty + i * 8][tx] = __float2half(W[(size_t)(k0 + ty + i * 8) * DD + n0 + tx]);
    __syncthreads();
#pragma unroll
    for (int i = 0; i < 4; i++)
        dst[(size_t)(n0 + ty + i * 8) * DD + k0 + tx] = t[tx][ty + i * 8];
}

// ---------------------------------------------------------------------------
// GEMM fp16 (QKV + O-proj): BM=64, BN=128, BK=64, 128 threads.
// grid.z selects w/b/out. z == vtz -> write output transposed into Vt.
// ---------------------------------------------------------------------------
#define XSP 72                       // halves per row (64 + 8 pad)
#define XT_H (64 * XSP)              // 4608
#define WT_H (128 * XSP)             // 9216
#define GEMM_SMEM_B ((2 * XT_H + 2 * WT_H) * 2 + 512 + 16)
#define NKCH 8

__global__ void __launch_bounds__(128) gemm_f16_kernel(
    const __half* __restrict__ X, const __half* __restrict__ WtBase, int wbase,
    const float* __restrict__ b0p, const float* __restrict__ b1p, const float* __restrict__ b2p,
    void* __restrict__ o0p, void* __restrict__ o1p, void* __restrict__ o2p,
    int out_half, int vtz)
{
    extern __shared__ __align__(16) __half smh[];
    __half* sx = smh;                      // [2][XT_H]
    __half* sw = smh + 2 * XT_H;           // [2][WT_H]
    float* bs = (float*)(smh + 2 * XT_H + 2 * WT_H);
    const uint32_t sxb = smem_u32(sx);
    const uint32_t swb = smem_u32(sw);

    const int z = blockIdx.z;
    const __half* Wt = WtBase + (size_t)(wbase + z) * DD * DD;
    const float* bias = (z == 0) ? b0p : (z == 1) ? b1p : b2p;
    void* Cout = (z == 0) ? o0p : (z == 1) ? o1p : o2p;

    const int tid = threadIdx.x;
    const int lane = tid & 31;
    const int wid = tid >> 5;
    const int wr = wid * 16;
    const int g = lane >> 2, q4 = lane & 3;
    const int m0 = blockIdx.y * 64;
    const int n0 = blockIdx.x * 128;

    const int lr = tid >> 3;            // 0..15
    const int lc = (tid & 7) * 8;       // halves column (16B chunks)

#pragma unroll
    for (int it = 0; it < 4; it++) {
        int r = lr + it * 16;
        cpasync16(sxb + (r * XSP + lc) * 2, &X[(size_t)(m0 + r) * DD + lc]);
    }
#pragma unroll
    for (int it = 0; it < 8; it++) {
        int r = lr + it * 16;
        cpasync16(swb + (r * XSP + lc) * 2, &Wt[(size_t)(n0 + r) * DD + lc]);
    }
    CP_COMMIT();
    if (tid < 128) bs[tid] = bias[n0 + tid];

    float c[16][4];
#pragma unroll
    for (int nt = 0; nt < 16; nt++)
#pragma unroll
        for (int j = 0; j < 4; j++) c[nt][j] = 0.0f;

    for (int ch = 0; ch < NKCH; ch++) {
        if (ch + 1 < NKCH) {
            const int k0 = (ch + 1) * 64;
            const int st = (ch + 1) & 1;
#pragma unroll
            for (int it = 0; it < 4; it++) {
                int r = lr + it * 16;
                cpasync16(sxb + (st * XT_H + r * XSP + lc) * 2, &X[(size_t)(m0 + r) * DD + k0 + lc]);
            }
#pragma unroll
            for (int it = 0; it < 8; it++) {
                int r = lr + it * 16;
                cpasync16(swb + (st * WT_H + r * XSP + lc) * 2, &Wt[(size_t)(n0 + r) * DD + k0 + lc]);
            }
        }
        CP_COMMIT();
        CP_WAIT1();
        __syncthreads();

        const __half* Xs = sx + (ch & 1) * XT_H;
        const __half* Ws = sw + (ch & 1) * WT_H;

#pragma unroll
        for (int ks = 0; ks < 4; ks++) {
            uint32_t a[4];
            const int ac = q4 * 2 + ks * 16;
            a[0] = *(const uint32_t*)&Xs[(wr + g) * XSP + ac];
            a[1] = *(const uint32_t*)&Xs[(wr + g + 8) * XSP + ac];
            a[2] = *(const uint32_t*)&Xs[(wr + g) * XSP + ac + 8];
            a[3] = *(const uint32_t*)&Xs[(wr + g + 8) * XSP + ac + 8];
#pragma unroll
            for (int nt = 0; nt < 16; nt++) {
                uint32_t b0 = *(const uint32_t*)&Ws[(nt * 8 + g) * XSP + ac];
                uint32_t b1 = *(const uint32_t*)&Ws[(nt * 8 + g) * XSP + ac + 8];
                mma16(c[nt], a, b0, b1);
            }
        }
        __syncthreads();
    }

    const int r0 = m0 + wr + g;
    if (z == vtz) {
        __half* stg = smh;   // 128*72 halves, reuse x buffers
        const int rl = wr + g;
#pragma unroll
        for (int nt = 0; nt < 16; nt++) {
            int colL = nt * 8 + q4 * 2;
            stg[colL * 72 + rl] = __float2half(c[nt][0] + bs[colL]);
            stg[(colL + 1) * 72 + rl] = __float2half(c[nt][1] + bs[colL + 1]);
            stg[colL * 72 + rl + 8] = __float2half(c[nt][2] + bs[colL]);
            stg[(colL + 1) * 72 + rl + 8] = __float2half(c[nt][3] + bs[colL + 1]);
        }
        __syncthreads();
        __half* Vt = (__half*)Cout;
        const int bb = m0 >> 11;
        const int t0 = m0 & (TT - 1);
#pragma unroll
        for (int it = 0; it < 8; it++) {
            int cidx = tid + it * 128;
            int colL = cidx >> 3;
            int tc = (cidx & 7) * 8;
            int n = n0 + colL;
            int hh = n >> 6, d = n & 63;
            uint4 v = *(uint4*)&stg[colL * 72 + tc];
            *(uint4*)&Vt[(size_t)((bb * HH + hh) * DH + d) * TT + t0 + tc] = v;
        }
    } else if (out_half) {
        __half* C = (__half*)Cout;
#pragma unroll
        for (int nt = 0; nt < 16; nt++) {
            int col = n0 + nt * 8 + q4 * 2;
            int bcol = nt * 8 + q4 * 2;
            uint32_t p0 = packh2(c[nt][0] + bs[bcol], c[nt][1] + bs[bcol + 1]);
            uint32_t p1 = packh2(c[nt][2] + bs[bcol], c[nt][3] + bs[bcol + 1]);
            *(uint32_t*)&C[(size_t)r0 * DD + col] = p0;
            *(uint32_t*)&C[(size_t)(r0 + 8) * DD + col] = p1;
        }
    } else {
        float* C = (float*)Cout;
#pragma unroll
        for (int nt = 0; nt < 16; nt++) {
            int col = n0 + nt * 8 + q4 * 2;
            int bcol = nt * 8 + q4 * 2;
            *(float2*)&C[(size_t)r0 * DD + col] =
                make_float2(c[nt][0] + bs[bcol], c[nt][1] + bs[bcol + 1]);
            *(float2*)&C[(size_t)(r0 + 8) * DD + col] =
                make_float2(c[nt][2] + bs[bcol], c[nt][3] + bs[bcol + 1]);
        }
    }
}

// ---------------------------------------------------------------------------
// Attention fp16. Grid (T/128, H, B), 128 threads (4 warps, m32 each).
// 3-stage cp.async pipeline (dynamic smem); ldmatrix.x4 B-frags; direct O.
// ---------------------------------------------------------------------------
#define KSP 72
#define AKT_H (KT * KSP)
#define ATTN_SMEM_B ((6 * AKT_H) * 2 + 512)

__global__ void __launch_bounds__(128) attn_f16_kernel(
    const __half* __restrict__ Q, const __half* __restrict__ K,
    const __half* __restrict__ Vt, const float* __restrict__ rb,
    __half* __restrict__ O)
{
    extern __shared__ __align__(16) __half sma[];
    __half* ks_ = sma;                    // [3][AKT_H]
    __half* vs_ = sma + 3 * AKT_H;        // [3][AKT_H]
    float* bias_s = (float*)(sma + 6 * AKT_H);
    const uint32_t kb = smem_u32(ks_);
    const uint32_t vb = smem_u32(vs_);

    const int tid = threadIdx.x;
    const int lane = tid & 31;
    const int wid = tid >> 5;
    const int wr = wid * 32;
    const int g = lane >> 2, q4 = lane & 3;
    const int q0 = blockIdx.x * 128;
    const int h = blockIdx.y, b = blockIdx.z;
    const int base = b * TT * DD + h * DH;
    const int vtbase = (b * HH + h) * DH * TT;

    const int lr = tid >> 3;
    const int lc = (tid & 7) * 8;

    const int grp = lane >> 3, lrow = lane & 7;
    const int lmoff = (((grp >> 1) * 8 + lrow) * KSP + (grp & 1) * 8) * 2;

    // prologue: stages 0 and 1
#pragma unroll
    for (int st = 0; st < 2; st++) {
        const int k0 = st * KT;
#pragma unroll
        for (int it = 0; it < 4; it++) {
            int r = lr + it * 16;
            cpasync16(kb + (st * AKT_H + r * KSP + lc) * 2, &K[base + (k0 + r) * DD + lc]);
            cpasync16(vb + (st * AKT_H + r * KSP + lc) * 2, &Vt[vtbase + r * TT + k0 + lc]);
        }
        CP_COMMIT();
    }

    if (tid < 2 * MAXREL + 1) bias_s[tid] = rb[h * (2 * MAXREL + 1) + tid] * L2E;
    const float blo = rb[h * (2 * MAXREL + 1)] * L2E;
    const float bhi = rb[h * (2 * MAXREL + 1) + 2 * MAXREL] * L2E;

    uint32_t qf[2][4][4];
#pragma unroll
    for (int ss = 0; ss < 2; ss++) {
        const int r = q0 + wr + ss * 16 + g;
#pragma unroll
        for (int ksi = 0; ksi < 4; ksi++) {
            const int ac = q4 * 2 + ksi * 16;
            qf[ss][ksi][0] = *(const uint32_t*)&Q[base + r * DD + ac];
            qf[ss][ksi][1] = *(const uint32_t*)&Q[base + (r + 8) * DD + ac];
            qf[ss][ksi][2] = *(const uint32_t*)&Q[base + r * DD + ac + 8];
            qf[ss][ksi][3] = *(const uint32_t*)&Q[base + (r + 8) * DD + ac + 8];
        }
    }

    float o[2][8][4];
#pragma unroll
    for (int ss = 0; ss < 2; ss++)
#pragma unroll
        for (int nt = 0; nt < 8; nt++)
#pragma unroll
            for (int j = 0; j < 4; j++) o[ss][nt][j] = 0.0f;
    float ls[2][2] = {{0.f, 0.f}, {0.f, 0.f}};

    for (int kt = 0; kt < NKT; kt++) {
        const int k0 = kt * KT;
        // issue tile kt+2 into buffer (kt+2)%3; empty commit in tail keeps
        // group accounting uniform (always exactly one commit per iteration)
        if (kt + 2 < NKT) {
            const int kn = (kt + 2) * KT;
            const int st = (kt + 2) % 3;
#pragma unroll
            for (int it = 0; it < 4; it++) {
                int r = lr + it * 16;
                cpasync16(kb + (st * AKT_H + r * KSP + lc) * 2, &K[base + (kn + r) * DD + lc]);
                cpasync16(vb + (st * AKT_H + r * KSP + lc) * 2, &Vt[vtbase + r * TT + kn + lc]);
            }
        }
        CP_COMMIT();
        CP_WAIT2();          // tile kt (commit #kt+1 of kt+3) has landed
        __syncthreads();

        const uint32_t kaddr = kb + (kt % 3) * AKT_H * 2 + lmoff;
        const uint32_t vaddr = vb + (kt % 3) * AKT_H * 2 + lmoff;

        float s[2][8][4];
#pragma unroll
        for (int ss = 0; ss < 2; ss++)
#pragma unroll
            for (int nt = 0; nt < 8; nt++)
#pragma unroll
                for (int j = 0; j < 4; j++) s[ss][nt][j] = 0.0f;

#pragma unroll
        for (int ksi = 0; ksi < 4; ksi++) {
#pragma unroll
            for (int ntp = 0; ntp < 4; ntp++) {
                uint32_t b0, b1, b2, b3;
                ldsm4(b0, b1, b2, b3, kaddr + (ntp * 16 * KSP + ksi * 16) * 2);
                mma16(s[0][2 * ntp], qf[0][ksi], b0, b1);
                mma16(s[1][2 * ntp], qf[1][ksi], b0, b1);
                mma16(s[0][2 * ntp + 1], qf[0][ksi], b2, b3);
                mma16(s[1][2 * ntp + 1], qf[1][ksi], b2, b3);
            }
        }

        const int dmin = q0 - (k0 + KT - 1);
        const int dmax = q0 + 127 - k0;
        if (dmin >= MAXREL) {
#pragma unroll
            for (int ss = 0; ss < 2; ss++)
#pragma unroll
                for (int nt = 0; nt < 8; nt++)
#pragma unroll
                    for (int j = 0; j < 4; j++)
                        s[ss][nt][j] = ex2(fmaf(s[ss][nt][j], SCALE_L2E, bhi));
        } else if (dmax <= -MAXREL) {
#pragma unroll
            for (int ss = 0; ss < 2; ss++)
#pragma unroll
                for (int nt = 0; nt < 8; nt++)
#pragma unroll
                    for (int j = 0; j < 4; j++)
                        s[ss][nt][j] = ex2(fmaf(s[ss][nt][j], SCALE_L2E, blo));
        } else {
#pragma unroll
            for (int ss = 0; ss < 2; ss++) {
                const int dr0 = q0 + wr + ss * 16 + g;
#pragma unroll
                for (int nt = 0; nt < 8; nt++) {
                    const int c0 = k0 + nt * 8 + q4 * 2;
#pragma unroll
                    for (int j = 0; j < 4; j++) {
                        int rel = (dr0 + ((j >> 1) << 3)) - (c0 + (j & 1));
                        rel = min(max(rel, -MAXREL), MAXREL) + MAXREL;
                        s[ss][nt][j] = ex2(fmaf(s[ss][nt][j], SCALE_L2E, bias_s[rel]));
                    }
                }
            }
        }
#pragma unroll
        for (int ss = 0; ss < 2; ss++)
#pragma unroll
            for (int nt = 0; nt < 8; nt++) {
                ls[ss][0] += s[ss][nt][0] + s[ss][nt][1];
                ls[ss][1] += s[ss][nt][2] + s[ss][nt][3];
            }

#pragma unroll
        for (int ksi = 0; ksi < 4; ksi++) {
            uint32_t a0[4], a1[4];
            a0[0] = packh2(s[0][2 * ksi][0], s[0][2 * ksi][1]);
            a0[1] = packh2(s[0][2 * ksi][2], s[0][2 * ksi][3]);
            a0[2] = packh2(s[0][2 * ksi + 1][0], s[0][2 * ksi + 1][1]);
            a0[3] = packh2(s[0][2 * ksi + 1][2], s[0][2 * ksi + 1][3]);
            a1[0] = packh2(s[1][2 * ksi][0], s[1][2 * ksi][1]);
            a1[1] = packh2(s[1][2 * ksi][2], s[1][2 * ksi][3]);
            a1[2] = packh2(s[1][2 * ksi + 1][0], s[1][2 * ksi + 1][1]);
            a1[3] = packh2(s[1][2 * ksi + 1][2], s[1][2 * ksi + 1][3]);
#pragma unroll
            for (int ntp = 0; ntp < 4; ntp++) {
                uint32_t b0, b1, b2, b3;
                ldsm4(b0, b1, b2, b3, vaddr + (ntp * 16 * KSP + ksi * 16) * 2);
                mma16(o[0][2 * ntp], a0, b0, b1);
                mma16(o[1][2 * ntp], a1, b0, b1);
                mma16(o[0][2 * ntp + 1], a0, b2, b3);
                mma16(o[1][2 * ntp + 1], a1, b2, b3);
            }
        }
        __syncthreads();
    }

#pragma unroll
    for (int ss = 0; ss < 2; ss++) {
#pragma unroll
        for (int j = 0; j < 2; j++) {
            ls[ss][j] += __shfl_xor_sync(0xffffffffu, ls[ss][j], 1);
            ls[ss][j] += __shfl_xor_sync(0xffffffffu, ls[ss][j], 2);
        }
        const float inv0 = 1.0f / ls[ss][0];
        const float inv1 = 1.0f / ls[ss][1];
        const int r0 = q0 + wr + ss * 16 + g;
#pragma unroll
        for (int nt = 0; nt < 8; nt++) {
            int col = nt * 8 + q4 * 2;
            uint32_t p0 = packh2(o[ss][nt][0] * inv0, o[ss][nt][1] * inv0);
            uint32_t p1 = packh2(o[ss][nt][2] * inv1, o[ss][nt][3] * inv1);
            *(uint32_t*)&O[base + r0 * DD + col] = p0;
            *(uint32_t*)&O[base + (r0 + 8) * DD + col] = p1;
        }
    }
}

// ---------------------------------------------------------------------------
extern "C" void kernel_launch(void* const* d_in, const int* in_sizes, int n_in,
                              void* d_out, int out_size)
{
    const float* hs = (const float*)d_in[0];
    const float* Wq = (const float*)d_in[1];
    const float* bq = (const float*)d_in[2];
    const float* Wk = (const float*)d_in[3];
    const float* bk = (const float*)d_in[4];
    const float* Wv = (const float*)d_in[5];
    const float* bv = (const float*)d_in[6];
    const float* Wo = (const float*)d_in[7];
    const float* bo = (const float*)d_in[8];
    const float* rb = (const float*)d_in[9];

    __half *pQ, *pK, *pVt, *pAO, *pX, *pW;
    cudaGetSymbolAddress((void**)&pQ, g_Qh);
    cudaGetSymbolAddress((void**)&pK, g_Kh);
    cudaGetSymbolAddress((void**)&pVt, g_Vth);
    cudaGetSymbolAddress((void**)&pAO, g_AOh);
    cudaGetSymbolAddress((void**)&pX, g_Xh);
    cudaGetSymbolAddress((void**)&pW, g_Wth);

    cudaFuncSetAttribute(gemm_f16_kernel,
                         cudaFuncAttributeMaxDynamicSharedMemorySize, GEMM_SMEM_B);
    cudaFuncSetAttribute(attn_f16_kernel,
                         cudaFuncAttributeMaxDynamicSharedMemorySize, ATTN_SMEM_B);

    // prep: z=0..3 weight transpose+cvt, z=4 hidden-state cvt
    prep_kernel<<<dim3(DD / 32, DD / 32, 5), dim3(32, 8)>>>(hs, Wq, Wk, Wv, Wo, pX, pW);

    // Fused Q/K/V projections; z==2 writes V transposed straight into Vt
    gemm_f16_kernel<<<dim3(DD / 128, BB * TT / 64, 3), 128, GEMM_SMEM_B>>>(
        pX, pW, 0, bq, bk, bv, pQ, pK, pVt, 1, 2);

    // Single-pass attention, 3-stage pipeline, direct half O
    attn_f16_kernel<<<dim3(TT / 128, HH, BB), 128, ATTN_SMEM_B>>>(pQ, pK, pVt, rb, pAO);

    // Output projection (wbase=3, fp32 out, no transpose)
    gemm_f16_kernel<<<dim3(DD / 128, BB * TT / 64, 1), 128, GEMM_SMEM_B>>>(
        pAO, pW, 3, bo, bo, bo, d_out, d_out, d_out, 0, -1);
}

// round 16
// speedup vs baseline: 1.5591x; 1.0068x over previous
#include <cuda_runtime.h>
#include <cuda_fp16.h>
#include <stdint.h>
#include <math.h>

#define TT 2048
#define BB 2
#define DD 512
#define HH 8
#define DH 64
#define MAXREL 32
#define SCALE_L2E 0.1803368801111244f   // (DH^-0.5) * log2(e)
#define L2E 1.4426950408889634f
#define KT 64                           // keys per attention tile
#define NKT (TT / KT)                   // 32 tiles

// Scratch (allocation-free rule: __device__ globals)
__device__ __half g_Qh[BB * TT * DD];
__device__ __half g_Kh[BB * TT * DD];
__device__ __half g_Vth[BB * HH * DH * TT];   // V transposed [b,h,d,t]
__device__ __half g_AOh[BB * TT * DD];
__device__ __half g_Xh[BB * TT * DD];         // hidden states, half
__device__ __half g_Wth[4 * DD * DD];         // W^T half: [n][k] for q,k,v,o

// ---------------------------------------------------------------------------
// helpers
// ---------------------------------------------------------------------------
__device__ __forceinline__ float ex2(float x) {
    float r;
    asm("ex2.approx.ftz.f32 %0, %1;" : "=f"(r) : "f"(x));
    return r;
}
__device__ __forceinline__ void mma16(float* d, const uint32_t* a, uint32_t b0, uint32_t b1) {
    asm volatile(
        "mma.sync.aligned.m16n8k16.row.col.f32.f16.f16.f32 "
        "{%0,%1,%2,%3}, {%4,%5,%6,%7}, {%8,%9}, {%0,%1,%2,%3};"
        : "+f"(d[0]), "+f"(d[1]), "+f"(d[2]), "+f"(d[3])
        : "r"(a[0]), "r"(a[1]), "r"(a[2]), "r"(a[3]), "r"(b0), "r"(b1));
}
__device__ __forceinline__ void ldsm4(uint32_t& r0, uint32_t& r1, uint32_t& r2, uint32_t& r3,
                                      uint32_t addr) {
    asm volatile("ldmatrix.sync.aligned.m8n8.x4.shared.b16 {%0,%1,%2,%3}, [%4];"
                 : "=r"(r0), "=r"(r1), "=r"(r2), "=r"(r3) : "r"(addr));
}
__device__ __forceinline__ uint32_t packh2(float lo, float hi) {
    __half2 h = __floats2half2_rn(lo, hi);
    return *(uint32_t*)&h;
}
__device__ __forceinline__ uint32_t smem_u32(const void* p) {
    uint32_t a;
    asm("{ .reg .u64 t; cvta.to.shared.u64 t, %1; cvt.u32.u64 %0, t; }" : "=r"(a) : "l"(p));
    return a;
}
__device__ __forceinline__ void cpasync16(uint32_t dst, const void* src) {
    asm volatile("cp.async.cg.shared.global [%0], [%1], 16;" :: "r"(dst), "l"(src));
}
#define CP_COMMIT() asm volatile("cp.async.commit_group;" ::: "memory")
#define CP_WAIT1()  asm volatile("cp.async.wait_group 1;" ::: "memory")

// ---------------------------------------------------------------------------
// Fused prep: z=0..3 -> W[k][n] fp32 -> Wt[n][k] half; z=4 -> hs fp32 -> half
// ---------------------------------------------------------------------------
__global__ void prep_kernel(const float* __restrict__ hs,
                            const float* __restrict__ W0, const float* __restrict__ W1,
                            const float* __restrict__ W2, const float* __restrict__ W3,
                            __half* __restrict__ Xh, __half* __restrict__ Wt)
{
    const int z = blockIdx.z;
    const int tx = threadIdx.x, ty = threadIdx.y;
    if (z == 4) {
        const int tidf = ty * 32 + tx;
        const int gb = blockIdx.y * gridDim.x + blockIdx.x;   // 0..255
        const float4* src = (const float4*)hs;
#pragma unroll
        for (int j = 0; j < 8; j++) {
            int i = gb * 2048 + j * 256 + tidf;
            float4 v = src[i];
            __half2 lo = __floats2half2_rn(v.x, v.y);
            __half2 hi = __floats2half2_rn(v.z, v.w);
            uint2 o = make_uint2(*(uint32_t*)&lo, *(uint32_t*)&hi);
            *(uint2*)&Xh[i * 4] = o;
        }
        return;
    }
    __shared__ __half t[32][33];
    const float* W = (z == 0) ? W0 : (z == 1) ? W1 : (z == 2) ? W2 : W3;
    __half* dst = Wt + (size_t)z * DD * DD;
    const int k0 = blockIdx.x * 32, n0 = blockIdx.y * 32;
#pragma unroll
    for (int i = 0; i < 4; i++)
        t[ty + i * 8][tx] = __float2half(W[(size_t)(k0 + ty + i * 8) * DD + n0 + tx]);
    __syncthreads();
#pragma unroll
    for (int i = 0; i < 4; i++)
        dst[(size_t)(n0 + ty + i * 8) * DD + k0 + tx] = t[tx][ty + i * 8];
}

// ---------------------------------------------------------------------------
// GEMM fp16 (QKV + O-proj): BM=64, BN=128, BK=64, 256 threads (8 warps 4m x 2n).
// grid.z selects w/b/out. z == vtz -> write output transposed into Vt.
// ---------------------------------------------------------------------------
#define XSP 72                       // halves per row (64 + 8 pad)
#define XT_H (64 * XSP)              // 4608
#define WT_H (128 * XSP)             // 9216
#define GEMM_SMEM_B ((2 * XT_H + 2 * WT_H) * 2 + 512 + 16)
#define NKCH 8

__global__ void __launch_bounds__(256) gemm_f16_kernel(
    const __half* __restrict__ X, const __half* __restrict__ WtBase, int wbase,
    const float* __restrict__ b0p, const float* __restrict__ b1p, const float* __restrict__ b2p,
    void* __restrict__ o0p, void* __restrict__ o1p, void* __restrict__ o2p,
    int out_half, int vtz)
{
    extern __shared__ __align__(16) __half smh[];
    __half* sx = smh;                      // [2][XT_H]
    __half* sw = smh + 2 * XT_H;           // [2][WT_H]
    float* bs = (float*)(smh + 2 * XT_H + 2 * WT_H);
    const uint32_t sxb = smem_u32(sx);
    const uint32_t swb = smem_u32(sw);

    const int z = blockIdx.z;
    const __half* Wt = WtBase + (size_t)(wbase + z) * DD * DD;
    const float* bias = (z == 0) ? b0p : (z == 1) ? b1p : b2p;
    void* Cout = (z == 0) ? o0p : (z == 1) ? o1p : o2p;

    const int tid = threadIdx.x;
    const int lane = tid & 31;
    const int wid = tid >> 5;            // 0..7
    const int wm = wid & 3;              // m-slab (16 rows)
    const int wn = wid >> 2;             // n-half (64 cols)
    const int wr = wm * 16;
    const int nb = wn * 64;
    const int g = lane >> 2, q4 = lane & 3;
    const int m0 = blockIdx.y * 64;
    const int n0 = blockIdx.x * 128;

    const int lr = tid >> 3;            // 0..31
    const int lc = (tid & 7) * 8;       // halves column (16B chunks)

    // prologue: stage 0
#pragma unroll
    for (int it = 0; it < 2; it++) {
        int r = lr + it * 32;
        cpasync16(sxb + (r * XSP + lc) * 2, &X[(size_t)(m0 + r) * DD + lc]);
    }
#pragma unroll
    for (int it = 0; it < 4; it++) {
        int r = lr + it * 32;
        cpasync16(swb + (r * XSP + lc) * 2, &Wt[(size_t)(n0 + r) * DD + lc]);
    }
    CP_COMMIT();
    if (tid < 128) bs[tid] = bias[n0 + tid];

    float c[8][4];
#pragma unroll
    for (int nt = 0; nt < 8; nt++)
#pragma unroll
        for (int j = 0; j < 4; j++) c[nt][j] = 0.0f;

    for (int ch = 0; ch < NKCH; ch++) {
        if (ch + 1 < NKCH) {
            const int k0 = (ch + 1) * 64;
            const int st = (ch + 1) & 1;
#pragma unroll
            for (int it = 0; it < 2; it++) {
                int r = lr + it * 32;
                cpasync16(sxb + (st * XT_H + r * XSP + lc) * 2, &X[(size_t)(m0 + r) * DD + k0 + lc]);
            }
#pragma unroll
            for (int it = 0; it < 4; it++) {
                int r = lr + it * 32;
                cpasync16(swb + (st * WT_H + r * XSP + lc) * 2, &Wt[(size_t)(n0 + r) * DD + k0 + lc]);
            }
        }
        CP_COMMIT();
        CP_WAIT1();
        __syncthreads();

        const __half* Xs = sx + (ch & 1) * XT_H;
        const __half* Ws = sw + (ch & 1) * WT_H;

#pragma unroll
        for (int ks = 0; ks < 4; ks++) {
            uint32_t a[4];
            const int ac = q4 * 2 + ks * 16;
            a[0] = *(const uint32_t*)&Xs[(wr + g) * XSP + ac];
            a[1] = *(const uint32_t*)&Xs[(wr + g + 8) * XSP + ac];
            a[2] = *(const uint32_t*)&Xs[(wr + g) * XSP + ac + 8];
            a[3] = *(const uint32_t*)&Xs[(wr + g + 8) * XSP + ac + 8];
#pragma unroll
            for (int nt = 0; nt < 8; nt++) {
                uint32_t b0 = *(const uint32_t*)&Ws[(nb + nt * 8 + g) * XSP + ac];
                uint32_t b1 = *(const uint32_t*)&Ws[(nb + nt * 8 + g) * XSP + ac + 8];
                mma16(c[nt], a, b0, b1);
            }
        }
        __syncthreads();
    }

    const int r0 = m0 + wr + g;
    if (z == vtz) {
        // Fused V transpose: stage [col][t_local] (pitch 72), write Vt [b,h,d,t]
        __half* stg = smh;   // 128*72 halves = 2*XT_H (x buffers, free now)
        const int rl = wr + g;
#pragma unroll
        for (int nt = 0; nt < 8; nt++) {
            int colL = nb + nt * 8 + q4 * 2;
            stg[colL * 72 + rl] = __float2half(c[nt][0] + bs[colL]);
            stg[(colL + 1) * 72 + rl] = __float2half(c[nt][1] + bs[colL + 1]);
            stg[colL * 72 + rl + 8] = __float2half(c[nt][2] + bs[colL]);
            stg[(colL + 1) * 72 + rl + 8] = __float2half(c[nt][3] + bs[colL + 1]);
        }
        __syncthreads();
        __half* Vt = (__half*)Cout;
        const int bb = m0 >> 11;
        const int t0 = m0 & (TT - 1);
#pragma unroll
        for (int it = 0; it < 4; it++) {
            int cidx = tid + it * 256;
            int colL = cidx >> 3;
            int tc = (cidx & 7) * 8;
            int n = n0 + colL;
            int hh = n >> 6, d = n & 63;
            uint4 v = *(uint4*)&stg[colL * 72 + tc];
            *(uint4*)&Vt[(size_t)((bb * HH + hh) * DH + d) * TT + t0 + tc] = v;
        }
    } else if (out_half) {
        __half* C = (__half*)Cout;
#pragma unroll
        for (int nt = 0; nt < 8; nt++) {
            int bcol = nb + nt * 8 + q4 * 2;
            int col = n0 + bcol;
            uint32_t p0 = packh2(c[nt][0] + bs[bcol], c[nt][1] + bs[bcol + 1]);
            uint32_t p1 = packh2(c[nt][2] + bs[bcol], c[nt][3] + bs[bcol + 1]);
            *(uint32_t*)&C[(size_t)r0 * DD + col] = p0;
            *(uint32_t*)&C[(size_t)(r0 + 8) * DD + col] = p1;
        }
    } else {
        float* C = (float*)Cout;
#pragma unroll
        for (int nt = 0; nt < 8; nt++) {
            int bcol = nb + nt * 8 + q4 * 2;
            int col = n0 + bcol;
            *(float2*)&C[(size_t)r0 * DD + col] =
                make_float2(c[nt][0] + bs[bcol], c[nt][1] + bs[bcol + 1]);
            *(float2*)&C[(size_t)(r0 + 8) * DD + col] =
                make_float2(c[nt][2] + bs[bcol], c[nt][3] + bs[bcol + 1]);
        }
    }
}

// ---------------------------------------------------------------------------
// Attention fp16 (R12 exact). Grid (T/128, H, B), 128 threads (4 warps, m32).
// 2-stage cp.async, ldmatrix.x4 B-frags, direct normalized half O write.
// ---------------------------------------------------------------------------
#define KSP 72
#define AKT_H (KT * KSP)

__global__ void __launch_bounds__(128) attn_f16_kernel(
    const __half* __restrict__ Q, const __half* __restrict__ K,
    const __half* __restrict__ Vt, const float* __restrict__ rb,
    __half* __restrict__ O)
{
    __shared__ __align__(16) __half ks_[2][AKT_H];
    __shared__ __align__(16) __half vs_[2][AKT_H];
    __shared__ float bias_s[72];
    const uint32_t kb = smem_u32(ks_);
    const uint32_t vb = smem_u32(vs_);

    const int tid = threadIdx.x;
    const int lane = tid & 31;
    const int wid = tid >> 5;
    const int wr = wid * 32;
    const int g = lane >> 2, q4 = lane & 3;
    const int q0 = blockIdx.x * 128;
    const int h = blockIdx.y, b = blockIdx.z;
    const int base = b * TT * DD + h * DH;
    const int vtbase = (b * HH + h) * DH * TT;

    const int lr = tid >> 3;
    const int lc = (tid & 7) * 8;

    const int grp = lane >> 3, lrow = lane & 7;
    const int lmoff = (((grp >> 1) * 8 + lrow) * KSP + (grp & 1) * 8) * 2;

#pragma unroll
    for (int it = 0; it < 4; it++) {
        int r = lr + it * 16;
        cpasync16(kb + (r * KSP + lc) * 2, &K[base + r * DD + lc]);
        cpasync16(vb + (r * KSP + lc) * 2, &Vt[vtbase + r * TT + lc]);
    }
    CP_COMMIT();

    if (tid < 2 * MAXREL + 1) bias_s[tid] = rb[h * (2 * MAXREL + 1) + tid] * L2E;
    const float blo = rb[h * (2 * MAXREL + 1)] * L2E;
    const float bhi = rb[h * (2 * MAXREL + 1) + 2 * MAXREL] * L2E;

    uint32_t qf[2][4][4];
#pragma unroll
    for (int ss = 0; ss < 2; ss++) {
        const int r = q0 + wr + ss * 16 + g;
#pragma unroll
        for (int ksi = 0; ksi < 4; ksi++) {
            const int ac = q4 * 2 + ksi * 16;
            qf[ss][ksi][0] = *(const uint32_t*)&Q[base + r * DD + ac];
            qf[ss][ksi][1] = *(const uint32_t*)&Q[base + (r + 8) * DD + ac];
            qf[ss][ksi][2] = *(const uint32_t*)&Q[base + r * DD + ac + 8];
            qf[ss][ksi][3] = *(const uint32_t*)&Q[base + (r + 8) * DD + ac + 8];
        }
    }

    float o[2][8][4];
#pragma unroll
    for (int ss = 0; ss < 2; ss++)
#pragma unroll
        for (int nt = 0; nt < 8; nt++)
#pragma unroll
            for (int j = 0; j < 4; j++) o[ss][nt][j] = 0.0f;
    float ls[2][2] = {{0.f, 0.f}, {0.f, 0.f}};

    for (int kt = 0; kt < NKT; kt++) {
        const int k0 = kt * KT;
        if (kt + 1 < NKT) {
            const int kn = (kt + 1) * KT;
            const int st = (kt + 1) & 1;
#pragma unroll
            for (int it = 0; it < 4; it++) {
                int r = lr + it * 16;
                cpasync16(kb + (st * AKT_H + r * KSP + lc) * 2, &K[base + (kn + r) * DD + lc]);
                cpasync16(vb + (st * AKT_H + r * KSP + lc) * 2, &Vt[vtbase + r * TT + kn + lc]);
            }
        }
        CP_COMMIT();
        CP_WAIT1();
        __syncthreads();

        const uint32_t kaddr = kb + (kt & 1) * AKT_H * 2 + lmoff;
        const uint32_t vaddr = vb + (kt & 1) * AKT_H * 2 + lmoff;

        float s[2][8][4];
#pragma unroll
        for (int ss = 0; ss < 2; ss++)
#pragma unroll
            for (int nt = 0; nt < 8; nt++)
#pragma unroll
                for (int j = 0; j < 4; j++) s[ss][nt][j] = 0.0f;

#pragma unroll
        for (int ksi = 0; ksi < 4; ksi++) {
#pragma unroll
            for (int ntp = 0; ntp < 4; ntp++) {
                uint32_t b0, b1, b2, b3;
                ldsm4(b0, b1, b2, b3, kaddr + (ntp * 16 * KSP + ksi * 16) * 2);
                mma16(s[0][2 * ntp], qf[0][ksi], b0, b1);
                mma16(s[1][2 * ntp], qf[1][ksi], b0, b1);
                mma16(s[0][2 * ntp + 1], qf[0][ksi], b2, b3);
                mma16(s[1][2 * ntp + 1], qf[1][ksi], b2, b3);
            }
        }

        const int dmin = q0 - (k0 + KT - 1);
        const int dmax = q0 + 127 - k0;
        if (dmin >= MAXREL) {
#pragma unroll
            for (int ss = 0; ss < 2; ss++)
#pragma unroll
                for (int nt = 0; nt < 8; nt++)
#pragma unroll
                    for (int j = 0; j < 4; j++)
                        s[ss][nt][j] = ex2(fmaf(s[ss][nt][j], SCALE_L2E, bhi));
        } else if (dmax <= -MAXREL) {
#pragma unroll
            for (int ss = 0; ss < 2; ss++)
#pragma unroll
                for (int nt = 0; nt < 8; nt++)
#pragma unroll
                    for (int j = 0; j < 4; j++)
                        s[ss][nt][j] = ex2(fmaf(s[ss][nt][j], SCALE_L2E, blo));
        } else {
#pragma unroll
            for (int ss = 0; ss < 2; ss++) {
                const int dr0 = q0 + wr + ss * 16 + g;
#pragma unroll
                for (int nt = 0; nt < 8; nt++) {
                    const int c0 = k0 + nt * 8 + q4 * 2;
#pragma unroll
                    for (int j = 0; j < 4; j++) {
                        int rel = (dr0 + ((j >> 1) << 3)) - (c0 + (j & 1));
                        rel = min(max(rel, -MAXREL), MAXREL) + MAXREL;
                        s[ss][nt][j] = ex2(fmaf(s[ss][nt][j], SCALE_L2E, bias_s[rel]));
                    }
                }
            }
        }
#pragma unroll
        for (int ss = 0; ss < 2; ss++)
#pragma unroll
            for (int nt = 0; nt < 8; nt++) {
                ls[ss][0] += s[ss][nt][0] + s[ss][nt][1];
                ls[ss][1] += s[ss][nt][2] + s[ss][nt][3];
            }

#pragma unroll
        for (int ksi = 0; ksi < 4; ksi++) {
            uint32_t a0[4], a1[4];
            a0[0] = packh2(s[0][2 * ksi][0], s[0][2 * ksi][1]);
            a0[1] = packh2(s[0][2 * ksi][2], s[0][2 * ksi][3]);
            a0[2] = packh2(s[0][2 * ksi + 1][0], s[0][2 * ksi + 1][1]);
            a0[3] = packh2(s[0][2 * ksi + 1][2], s[0][2 * ksi + 1][3]);
            a1[0] = packh2(s[1][2 * ksi][0], s[1][2 * ksi][1]);
            a1[1] = packh2(s[1][2 * ksi][2], s[1][2 * ksi][3]);
            a1[2] = packh2(s[1][2 * ksi + 1][0], s[1][2 * ksi + 1][1]);
            a1[3] = packh2(s[1][2 * ksi + 1][2], s[1][2 * ksi + 1][3]);
#pragma unroll
            for (int ntp = 0; ntp < 4; ntp++) {
                uint32_t b0, b1, b2, b3;
                ldsm4(b0, b1, b2, b3, vaddr + (ntp * 16 * KSP + ksi * 16) * 2);
                mma16(o[0][2 * ntp], a0, b0, b1);
                mma16(o[1][2 * ntp], a1, b0, b1);
                mma16(o[0][2 * ntp + 1], a0, b2, b3);
                mma16(o[1][2 * ntp + 1], a1, b2, b3);
            }
        }
        __syncthreads();
    }

#pragma unroll
    for (int ss = 0; ss < 2; ss++) {
#pragma unroll
        for (int j = 0; j < 2; j++) {
            ls[ss][j] += __shfl_xor_sync(0xffffffffu, ls[ss][j], 1);
            ls[ss][j] += __shfl_xor_sync(0xffffffffu, ls[ss][j], 2);
        }
        const float inv0 = 1.0f / ls[ss][0];
        const float inv1 = 1.0f / ls[ss][1];
        const int r0 = q0 + wr + ss * 16 + g;
#pragma unroll
        for (int nt = 0; nt < 8; nt++) {
            int col = nt * 8 + q4 * 2;
            uint32_t p0 = packh2(o[ss][nt][0] * inv0, o[ss][nt][1] * inv0);
            uint32_t p1 = packh2(o[ss][nt][2] * inv1, o[ss][nt][3] * inv1);
            *(uint32_t*)&O[base + r0 * DD + col] = p0;
            *(uint32_t*)&O[base + (r0 + 8) * DD + col] = p1;
        }
    }
}

// ---------------------------------------------------------------------------
extern "C" void kernel_launch(void* const* d_in, const int* in_sizes, int n_in,
                              void* d_out, int out_size)
{
    const float* hs = (const float*)d_in[0];
    const float* Wq = (const float*)d_in[1];
    const float* bq = (const float*)d_in[2];
    const float* Wk = (const float*)d_in[3];
    const float* bk = (const float*)d_in[4];
    const float* Wv = (const float*)d_in[5];
    const float* bv = (const float*)d_in[6];
    const float* Wo = (const float*)d_in[7];
    const float* bo = (const float*)d_in[8];
    const float* rb = (const float*)d_in[9];

    __half *pQ, *pK, *pVt, *pAO, *pX, *pW;
    cudaGetSymbolAddress((void**)&pQ, g_Qh);
    cudaGetSymbolAddress((void**)&pK, g_Kh);
    cudaGetSymbolAddress((void**)&pVt, g_Vth);
    cudaGetSymbolAddress((void**)&pAO, g_AOh);
    cudaGetSymbolAddress((void**)&pX, g_Xh);
    cudaGetSymbolAddress((void**)&pW, g_Wth);

    cudaFuncSetAttribute(gemm_f16_kernel,
                         cudaFuncAttributeMaxDynamicSharedMemorySize, GEMM_SMEM_B);

    // prep: z=0..3 weight transpose+cvt, z=4 hidden-state cvt
    prep_kernel<<<dim3(DD / 32, DD / 32, 5), dim3(32, 8)>>>(hs, Wq, Wk, Wv, Wo, pX, pW);

    // Fused Q/K/V projections; z==2 writes V transposed straight into Vt
    gemm_f16_kernel<<<dim3(DD / 128, BB * TT / 64, 3), 256, GEMM_SMEM_B>>>(
        pX, pW, 0, bq, bk, bv, pQ, pK, pVt, 1, 2);

    // Single-pass attention (R12 exact), direct half O
    attn_f16_kernel<<<dim3(TT / 128, HH, BB), 128>>>(pQ, pK, pVt, rb, pAO);

    // Output projection (wbase=3, fp32 out, no transpose)
    gemm_f16_kernel<<<dim3(DD / 128, BB * TT / 64, 1), 256, GEMM_SMEM_B>>>(
        pAO, pW, 3, bo, bo, bo, d_out, d_out, d_out, 0, -1);
}